// round 1
// baseline (speedup 1.0000x reference)
#include <cuda_runtime.h>
#include <math.h>

#define B_   256
#define L_   2048
#define E_   64
#define DA_  64
#define R_   32
#define LT_  64                 // tokens per tile
#define NTILES_ (L_ / LT_)
#define NTHR_ 256

// shared memory layout (float offsets)
#define OFF_W1T 0                       // [e*64 + d]      (W1 transposed)
#define OFF_W2T (OFF_W1T + 64*64)       // [d*32 + r]      (W2 transposed)
#define OFF_XE  (OFF_W2T + 64*32)       // [e*65 + j]      (xm, e-major, odd stride: scalar reads)
#define OFF_XJ  (OFF_XE  + 64*65)       // [j*68 + e]      (xm, token-major, vec4 reads)
#define OFF_H   (OFF_XJ  + 64*68)       // [d*68 + j]
#define OFF_A   (OFF_H   + 64*68)       // [r*68 + k]
#define OFF_M   (OFF_A   + 32*68)       // [64] mask tile
#define OFF_DEN (OFF_M   + 64)          // [32] denominators
#define SMEM_FLOATS (OFF_DEN + 32)
#define SMEM_BYTES  (SMEM_FLOATS * 4)

__global__ void __launch_bounds__(NTHR_, 2)
selfbi_kernel(const float* __restrict__ x,
              const float* __restrict__ mask,
              const float* __restrict__ W1,
              const float* __restrict__ W2,
              float* __restrict__ out)
{
    extern __shared__ float sm[];
    float* sW1T = sm + OFF_W1T;
    float* sW2T = sm + OFF_W2T;
    float* sXe  = sm + OFF_XE;
    float* sXj  = sm + OFF_XJ;
    float* sH   = sm + OFF_H;
    float* sA   = sm + OFF_A;
    float* sM   = sm + OFF_M;
    float* sDen = sm + OFF_DEN;

    const int tid = threadIdx.x;
    const int b   = blockIdx.x;

    const float* xb = x    + (long)b * L_ * E_;
    const float* mb = mask + (long)b * L_;

    // ---- one-time: load weights transposed into SMEM ----
    for (int i = tid; i < DA_ * E_; i += NTHR_) {
        int d = i >> 6, e = i & 63;
        sW1T[e * 64 + d] = W1[i];          // W1 is (DA,E) row-major
    }
    for (int i = tid; i < R_ * DA_; i += NTHR_) {
        int r = i >> 6, d = i & 63;
        sW2T[d * 32 + r] = W2[i];          // W2 is (R,DA) row-major
    }
    if (tid < R_) sDen[tid] = 0.0f;

    // ---- thread tilings ----
    const int g1_d0 = (tid & 15) * 4;      // GEMM1: 4 d x 4 j per thread
    const int g1_j0 = (tid >> 4) * 4;
    const int g2_r0 = (tid & 15) * 2;      // GEMM2: 2 r x 4 j per thread
    const int g2_j0 = (tid >> 4) * 4;
    const int g3_r0 = (tid >> 4) * 2;      // GEMM3: 2 r x 4 e per thread (persistent)
    const int g3_e0 = (tid & 15) * 4;

    float acc3[2][4] = {{0.f,0.f,0.f,0.f},{0.f,0.f,0.f,0.f}};  // numer accumulators
    float dp0 = 0.f, dp1 = 0.f;                                 // denom partials

    for (int t = 0; t < NTILES_; ++t) {
        const int l0 = t * LT_;
        __syncthreads();   // previous tile's consumers done before overwrite

        // ---- load + mask: x tile into both layouts ----
        if (tid < LT_) sM[tid] = mb[l0 + tid];
        #pragma unroll
        for (int rep = 0; rep < 4; ++rep) {
            int idx = rep * NTHR_ + tid;      // 0..1023
            int j   = idx >> 4;
            int ec  = idx & 15;
            float m = __ldg(&mb[l0 + j]);
            float4 v = *reinterpret_cast<const float4*>(&xb[(long)(l0 + j) * E_ + ec * 4]);
            v.x *= m; v.y *= m; v.z *= m; v.w *= m;
            *reinterpret_cast<float4*>(&sXj[j * 68 + ec * 4]) = v;
            int e0 = ec * 4;
            sXe[(e0 + 0) * 65 + j] = v.x;
            sXe[(e0 + 1) * 65 + j] = v.y;
            sXe[(e0 + 2) * 65 + j] = v.z;
            sXe[(e0 + 3) * 65 + j] = v.w;
        }
        __syncthreads();

        // ---- GEMM1: H = tanh(W1 @ Xm), output [d][j] ----
        {
            float a1[4][4];
            #pragma unroll
            for (int i = 0; i < 4; ++i)
                #pragma unroll
                for (int jj = 0; jj < 4; ++jj) a1[i][jj] = 0.f;

            #pragma unroll 8
            for (int e = 0; e < E_; ++e) {
                float4 wv = *reinterpret_cast<const float4*>(&sW1T[e * 64 + g1_d0]);
                float x0 = sXe[e * 65 + g1_j0 + 0];
                float x1 = sXe[e * 65 + g1_j0 + 1];
                float x2 = sXe[e * 65 + g1_j0 + 2];
                float x3 = sXe[e * 65 + g1_j0 + 3];
                a1[0][0] += wv.x * x0; a1[0][1] += wv.x * x1; a1[0][2] += wv.x * x2; a1[0][3] += wv.x * x3;
                a1[1][0] += wv.y * x0; a1[1][1] += wv.y * x1; a1[1][2] += wv.y * x2; a1[1][3] += wv.y * x3;
                a1[2][0] += wv.z * x0; a1[2][1] += wv.z * x1; a1[2][2] += wv.z * x2; a1[2][3] += wv.z * x3;
                a1[3][0] += wv.w * x0; a1[3][1] += wv.w * x1; a1[3][2] += wv.w * x2; a1[3][3] += wv.w * x3;
            }
            #pragma unroll
            for (int i = 0; i < 4; ++i) {
                float4 hv;
                hv.x = tanhf(a1[i][0]);
                hv.y = tanhf(a1[i][1]);
                hv.z = tanhf(a1[i][2]);
                hv.w = tanhf(a1[i][3]);
                *reinterpret_cast<float4*>(&sH[(g1_d0 + i) * 68 + g1_j0]) = hv;
            }
        }
        __syncthreads();

        // ---- GEMM2: Q = W2 @ H, then A = exp(Q)*mask ----
        {
            float a2[2][4] = {{0.f,0.f,0.f,0.f},{0.f,0.f,0.f,0.f}};
            #pragma unroll 8
            for (int d = 0; d < DA_; ++d) {
                float2 wv = *reinterpret_cast<const float2*>(&sW2T[d * 32 + g2_r0]);
                float4 hv = *reinterpret_cast<const float4*>(&sH[d * 68 + g2_j0]);
                a2[0][0] += wv.x * hv.x; a2[0][1] += wv.x * hv.y;
                a2[0][2] += wv.x * hv.z; a2[0][3] += wv.x * hv.w;
                a2[1][0] += wv.y * hv.x; a2[1][1] += wv.y * hv.y;
                a2[1][2] += wv.y * hv.z; a2[1][3] += wv.y * hv.w;
            }
            float m0 = sM[g2_j0 + 0], m1 = sM[g2_j0 + 1];
            float m2 = sM[g2_j0 + 2], m3 = sM[g2_j0 + 3];
            float4 v0, v1;
            v0.x = expf(a2[0][0]) * m0;  v0.y = expf(a2[0][1]) * m1;
            v0.z = expf(a2[0][2]) * m2;  v0.w = expf(a2[0][3]) * m3;
            v1.x = expf(a2[1][0]) * m0;  v1.y = expf(a2[1][1]) * m1;
            v1.z = expf(a2[1][2]) * m2;  v1.w = expf(a2[1][3]) * m3;
            dp0 += (v0.x + v0.y) + (v0.z + v0.w);
            dp1 += (v1.x + v1.y) + (v1.z + v1.w);
            *reinterpret_cast<float4*>(&sA[(g2_r0 + 0) * 68 + g2_j0]) = v0;
            *reinterpret_cast<float4*>(&sA[(g2_r0 + 1) * 68 + g2_j0]) = v1;
        }
        __syncthreads();

        // ---- GEMM3: numer += A @ Xm^T  (accumulate in registers) ----
        {
            #pragma unroll 8
            for (int k = 0; k < LT_; ++k) {
                float av0 = sA[(g3_r0 + 0) * 68 + k];
                float av1 = sA[(g3_r0 + 1) * 68 + k];
                float4 xv = *reinterpret_cast<const float4*>(&sXj[k * 68 + g3_e0]);
                acc3[0][0] += av0 * xv.x; acc3[0][1] += av0 * xv.y;
                acc3[0][2] += av0 * xv.z; acc3[0][3] += av0 * xv.w;
                acc3[1][0] += av1 * xv.x; acc3[1][1] += av1 * xv.y;
                acc3[1][2] += av1 * xv.z; acc3[1][3] += av1 * xv.w;
            }
        }
    }

    // ---- denominator reduction ----
    atomicAdd(&sDen[g2_r0 + 0], dp0);
    atomicAdd(&sDen[g2_r0 + 1], dp1);
    __syncthreads();

    // ---- finalize + write out (B,R,E) ----
    const float inv0 = 1.0f / sDen[g3_r0 + 0];
    const float inv1 = 1.0f / sDen[g3_r0 + 1];
    float4 o0, o1;
    o0.x = acc3[0][0] * inv0; o0.y = acc3[0][1] * inv0;
    o0.z = acc3[0][2] * inv0; o0.w = acc3[0][3] * inv0;
    o1.x = acc3[1][0] * inv1; o1.y = acc3[1][1] * inv1;
    o1.z = acc3[1][2] * inv1; o1.w = acc3[1][3] * inv1;
    float* ob = out + (long)b * R_ * E_;
    *reinterpret_cast<float4*>(&ob[(g3_r0 + 0) * E_ + g3_e0]) = o0;
    *reinterpret_cast<float4*>(&ob[(g3_r0 + 1) * E_ + g3_e0]) = o1;
}

extern "C" void kernel_launch(void* const* d_in, const int* in_sizes, int n_in,
                              void* d_out, int out_size)
{
    const float* x    = (const float*)d_in[0];
    const float* mask = (const float*)d_in[1];
    const float* W1   = (const float*)d_in[2];
    const float* W2   = (const float*)d_in[3];
    float* out        = (float*)d_out;

    cudaFuncSetAttribute(selfbi_kernel,
                         cudaFuncAttributeMaxDynamicSharedMemorySize, SMEM_BYTES);
    selfbi_kernel<<<B_, NTHR_, SMEM_BYTES>>>(x, mask, W1, W2, out);
}